// round 1
// baseline (speedup 1.0000x reference)
#include <cuda_runtime.h>

#define B_    64
#define S_    512
#define DIN   512
#define NCAP  32
#define DCAP  64
#define EPSQ  1e-7f

// ---------------- scratch (device globals; no allocations) ----------------
__device__ float g_t[B_ * DIN];            // column sums of U (iter-0 "v", n-independent)
__device__ float g_v[B_ * NCAP * DIN];     // v[b,n,i] = sum_s c * U
__device__ float g_w[B_ * NCAP * DIN];     // w[b,n,i] = sum_d out * W
__device__ float g_c[B_ * S_ * NCAP];      // logits -> (in-place softmax) -> c, layout (b,s,n)

// ---------------- t[b,i] = sum_s U[b,s,i] ----------------
__global__ __launch_bounds__(128) void colsum_k(const float* __restrict__ U) {
    int b = blockIdx.y;
    int i = blockIdx.x * 128 + threadIdx.x;
    const float* p = U + (size_t)b * S_ * DIN + i;
    float a0 = 0.f, a1 = 0.f, a2 = 0.f, a3 = 0.f;
    #pragma unroll 4
    for (int s = 0; s < S_; s += 4) {
        a0 += p[(size_t)(s    ) * DIN];
        a1 += p[(size_t)(s + 1) * DIN];
        a2 += p[(size_t)(s + 2) * DIN];
        a3 += p[(size_t)(s + 3) * DIN];
    }
    g_t[b * DIN + i] = a0 + a1 + a2 + a3;
}

// ---------------- outputs[b,n,:] = squash(v[b,n,:] @ W[:, n*64:+64]) ----------------
// grid (8 b-groups, 32 n), block 256. W block per n = 128KB, reused across 8 b's via L1.
__global__ __launch_bounds__(256) void out_k(const float* __restrict__ W,
                                             float* __restrict__ out, int bcast) {
    int n  = blockIdx.y;
    int b0 = blockIdx.x * 8;
    __shared__ float sv[DIN];
    __shared__ float red[256];
    __shared__ float so[DCAP];
    __shared__ float swsum[2];
    const float* Wn = W + n * DCAP;
    int tid  = threadIdx.x;
    int d    = tid & 63;
    int part = tid >> 6;   // 0..3, each covers 128 of the 512 i's
    for (int bb = 0; bb < 8; ++bb) {
        int b = b0 + bb;
        const float* v = bcast ? (g_t + (size_t)b * DIN)
                               : (g_v + ((size_t)b * NCAP + n) * DIN);
        sv[tid]       = v[tid];
        sv[256 + tid] = v[256 + tid];
        __syncthreads();
        float a0 = 0.f, a1 = 0.f, a2 = 0.f, a3 = 0.f;
        int ib = part * 128;
        #pragma unroll 8
        for (int k = 0; k < 128; k += 4) {
            a0 += sv[ib + k    ] * Wn[(size_t)(ib + k    ) * 2048 + d];
            a1 += sv[ib + k + 1] * Wn[(size_t)(ib + k + 1) * 2048 + d];
            a2 += sv[ib + k + 2] * Wn[(size_t)(ib + k + 2) * 2048 + d];
            a3 += sv[ib + k + 3] * Wn[(size_t)(ib + k + 3) * 2048 + d];
        }
        red[tid] = a0 + a1 + a2 + a3;
        __syncthreads();
        if (part == 0) {
            float o = red[d] + red[64 + d] + red[128 + d] + red[192 + d];
            if (bcast) o *= (1.0f / 32.0f);   // uniform softmax of zero logits
            so[d] = o;
            float sq = o * o;
            #pragma unroll
            for (int off = 16; off; off >>= 1)
                sq += __shfl_xor_sync(0xffffffffu, sq, off);
            if ((tid & 31) == 0) swsum[tid >> 5] = sq;
        }
        __syncthreads();
        if (part == 0) {
            float rn = rsqrtf(swsum[0] + swsum[1] + EPSQ);
            out[((size_t)b * NCAP + n) * DCAP + d] = so[d] * rn;
        }
        __syncthreads();
    }
}

// ---------------- w[b,n,i] = sum_d out[b,n,d] * W[i, n*64+d] ----------------
// grid (8 b-groups, 32 n), block 512 (thread = i). W block reused across b via L1.
__global__ __launch_bounds__(512) void w_k(const float* __restrict__ outp,
                                           const float* __restrict__ W) {
    int n  = blockIdx.y;
    int b0 = blockIdx.x * 8;
    __shared__ float so[DCAP];
    int tid = threadIdx.x;
    const float4* wr = (const float4*)(W + n * DCAP + (size_t)tid * 2048);
    for (int bb = 0; bb < 8; ++bb) {
        int b = b0 + bb;
        if (tid < DCAP) so[tid] = outp[((size_t)b * NCAP + n) * DCAP + tid];
        __syncthreads();
        float acc = 0.f;
        #pragma unroll
        for (int q = 0; q < 16; ++q) {
            float4 wv = wr[q];
            acc += so[q * 4 + 0] * wv.x + so[q * 4 + 1] * wv.y
                 + so[q * 4 + 2] * wv.z + so[q * 4 + 3] * wv.w;
        }
        g_w[((size_t)b * NCAP + n) * DIN + tid] = acc;
        __syncthreads();
    }
}

// ---------------- blog[b,s,n] = sum_i U[b,s,i] * w[b,n,i] ----------------
// per-b GEMM (512s x 512i) @ (512i x 32n), tile 128s x 32n, grid (4,64), block 256.
__global__ __launch_bounds__(256) void blog_k(const float* __restrict__ U) {
    int b  = blockIdx.y;
    int s0 = blockIdx.x * 128;
    __shared__ float su[128 * 33];   // [s][k], pad 33
    __shared__ float sw[32 * 33];    // [k][n], pad 33
    int tid = threadIdx.x;
    int tn  = (tid & 7) * 4;         // n0 (covers 0..31)
    int ts  = (tid >> 3) * 4;        // s0 local (covers 0..127)
    float acc[4][4] = {};
    const float* Ub = U   + (size_t)b * S_ * DIN;
    const float* wb = g_w + (size_t)b * NCAP * DIN;
    for (int k0 = 0; k0 < DIN; k0 += 32) {
        {   // U tile 128s x 32k
            int k  = tid & 31;
            int sb = tid >> 5;       // 0..7
            #pragma unroll
            for (int r = 0; r < 16; ++r) {
                int s = sb + r * 8;
                su[s * 33 + k] = Ub[(size_t)(s0 + s) * DIN + k0 + k];
            }
        }
        {   // w tile 32k x 32n
            int k  = tid & 31;
            int nb = tid >> 5;
            #pragma unroll
            for (int r = 0; r < 4; ++r) {
                int n = nb + r * 8;
                sw[k * 33 + n] = wb[(size_t)n * DIN + k0 + k];
            }
        }
        __syncthreads();
        #pragma unroll
        for (int kk = 0; kk < 32; ++kk) {
            float av[4], bv[4];
            #pragma unroll
            for (int j = 0; j < 4; ++j) av[j] = su[(ts + j) * 33 + kk];
            #pragma unroll
            for (int j = 0; j < 4; ++j) bv[j] = sw[kk * 33 + tn + j];
            #pragma unroll
            for (int x = 0; x < 4; ++x)
                #pragma unroll
                for (int y = 0; y < 4; ++y)
                    acc[x][y] += av[x] * bv[y];
        }
        __syncthreads();
    }
    float* cb = g_c + ((size_t)b * S_ + s0) * NCAP;
    #pragma unroll
    for (int x = 0; x < 4; ++x) {
        float4 vv = make_float4(acc[x][0], acc[x][1], acc[x][2], acc[x][3]);
        *(float4*)(cb + (size_t)(ts + x) * NCAP + tn) = vv;
    }
}

// ---------------- in-place softmax over n (32 contiguous), warp per (b,s) ----------------
__global__ __launch_bounds__(256) void softmax_k() {
    int warp = threadIdx.x >> 5;
    int lane = threadIdx.x & 31;
    size_t bs = (size_t)blockIdx.x * 8 + warp;   // < 32768
    float x = g_c[bs * NCAP + lane];
    float m = x;
    #pragma unroll
    for (int off = 16; off; off >>= 1) m = fmaxf(m, __shfl_xor_sync(0xffffffffu, m, off));
    float e = __expf(x - m);
    float sum = e;
    #pragma unroll
    for (int off = 16; off; off >>= 1) sum += __shfl_xor_sync(0xffffffffu, sum, off);
    g_c[bs * NCAP + lane] = e / sum;
}

// ---------------- v[b,n,i] = sum_s c[b,s,n] * U[b,s,i] ----------------
// per-b GEMM (32n x 512s) @ (512s x 512i), tile 32n x 128i, grid (4,64), block 256.
__global__ __launch_bounds__(256) void v_k(const float* __restrict__ U) {
    int b  = blockIdx.y;
    int i0 = blockIdx.x * 128;
    __shared__ float sc[32 * 33];    // [k(s)][n]
    __shared__ float su[32 * 129];   // [k(s)][i], pad 129
    int tid = threadIdx.x;
    int tn  = (tid & 7) * 4;         // n (0..31)
    int ti  = (tid >> 3) * 4;        // i local (0..127)
    float acc[4][4] = {};
    const float* Ub = U   + (size_t)b * S_ * DIN;
    const float* cb = g_c + (size_t)b * S_ * NCAP;
    for (int k0 = 0; k0 < S_; k0 += 32) {
        {   // c tile 32s x 32n
            int n  = tid & 31;
            int sb = tid >> 5;
            #pragma unroll
            for (int r = 0; r < 4; ++r) {
                int s = sb + r * 8;
                sc[s * 33 + n] = cb[(size_t)(k0 + s) * NCAP + n];
            }
        }
        {   // U tile 32s x 128i
            int il = tid & 127;
            int sb = tid >> 7;       // 0..1
            #pragma unroll
            for (int r = 0; r < 16; ++r) {
                int s = sb + r * 2;
                su[s * 129 + il] = Ub[(size_t)(k0 + s) * DIN + i0 + il];
            }
        }
        __syncthreads();
        #pragma unroll
        for (int kk = 0; kk < 32; ++kk) {
            float av[4], bv[4];
            #pragma unroll
            for (int j = 0; j < 4; ++j) av[j] = sc[kk * 33 + tn + j];
            #pragma unroll
            for (int j = 0; j < 4; ++j) bv[j] = su[kk * 129 + ti + j];
            #pragma unroll
            for (int x = 0; x < 4; ++x)
                #pragma unroll
                for (int y = 0; y < 4; ++y)
                    acc[x][y] += av[x] * bv[y];
        }
        __syncthreads();
    }
    float* vb = g_v + (size_t)b * NCAP * DIN + i0;
    #pragma unroll
    for (int x = 0; x < 4; ++x) {
        float4 vv = make_float4(acc[x][0], acc[x][1], acc[x][2], acc[x][3]);
        *(float4*)(vb + (size_t)(tn + x) * DIN + ti) = vv;
    }
}

// ---------------- launch ----------------
extern "C" void kernel_launch(void* const* d_in, const int* in_sizes, int n_in,
                              void* d_out, int out_size) {
    const float* U = (const float*)d_in[0];   // (64, 512, 512)
    const float* W = (const float*)d_in[1];   // (512, 2048)
    float* out = (float*)d_out;               // (64, 32, 64)

    colsum_k<<<dim3(4, B_), 128>>>(U);
    out_k<<<dim3(8, NCAP), 256>>>(W, out, 1);          // iteration 0 (uniform c)
    for (int it = 0; it < 2; ++it) {
        w_k<<<dim3(8, NCAP), 512>>>(out, W);
        blog_k<<<dim3(4, B_), 256>>>(U);
        softmax_k<<<(B_ * S_) / 8, 256>>>();
        v_k<<<dim3(4, B_), 256>>>(U);
        out_k<<<dim3(8, NCAP), 256>>>(W, out, 0);      // iterations 1, 2
    }
}